// round 10
// baseline (speedup 1.0000x reference)
#include <cuda_runtime.h>
#include <cuda_bf16.h>

// RNN_72541997629806: 5-layer stacked LSTM (H=4), SEQ=610, BATCH=128,
// per-t Linear(4->1) + final FC [5,610] -> out [128,5].
//
// R10: one warp = one batch element; 2 timesteps per round (R9 skeleton),
//   op-count trimmed per the rt-sum model:
//   - serial 4xfma2 + hadd gate dots (5 ops/gate)
//   - 2h-publish folding: H = fma(T3,tc,tc) = 2h; all h-consuming weight
//     columns pre-scaled by 0.5 (wh, wi stages>=1, w_lin)
//   - c-update: u=fma(T1,c,c), v=fma(T0,gt,gt), c=0.5(u+v)
//   - stage 0 reads x directly from SMEM (packed select; injection lanes gone)
//   - vector LDS: x LDS.128/round, w_fc rows LDS.64/round

#define SEQ 610
#define BATCH 128
#define ROUNDS 310           // r = 0..309 ; stage5 t1 = 2*309-10+1 = 609
#define XS_N 624
#define WFC_N 624            // valid data at [10, 620)

typedef unsigned long long ull;

__device__ __forceinline__ float tanh_fast(float x) {
    float y;
    asm("tanh.approx.f32 %0, %1;" : "=f"(y) : "f"(x));
    return y;
}
__device__ __forceinline__ ull pk2(float lo, float hi) {
    ull r; asm("mov.b64 %0, {%1, %2};" : "=l"(r) : "f"(lo), "f"(hi)); return r;
}
__device__ __forceinline__ ull fma2(ull a, ull b, ull c) {
    ull d; asm("fma.rn.f32x2 %0, %1, %2, %3;" : "=l"(d) : "l"(a), "l"(b), "l"(c)); return d;
}
__device__ __forceinline__ float hadd2(ull v) {
    float lo, hi; asm("mov.b64 {%0, %1}, %2;" : "=f"(lo), "=f"(hi) : "l"(v)); return lo + hi;
}

__global__ __launch_bounds__(32, 1)
void lstm_warp_kernel(const float* __restrict__ x,      // [128,610,2]
                      const float* __restrict__ w_ih0,  // [16,2]
                      const float* __restrict__ w_ih,   // [4,16,4]
                      const float* __restrict__ w_hh,   // [5,16,4]
                      const float* __restrict__ b_ih,   // [5,16]
                      const float* __restrict__ b_hh,   // [5,16]
                      const float* __restrict__ w_lin,  // [1,4]
                      const float* __restrict__ b_lin,  // [1]
                      const float* __restrict__ w_fc,   // [5,610]
                      const float* __restrict__ b_fc,   // [5]
                      float* __restrict__ out)          // [128,5]
{
    const int lane  = threadIdx.x;
    const int stage = lane >> 2;             // 0..7
    const int j     = lane & 3;
    const int b     = blockIdx.x;
    const int pbase = (lane - 4) & 28;       // base lane of previous stage quad
    const bool isS0 = (stage == 0);

    // ---- packed per-lane weights ----
    // Scales: sc(q) = 0.5 for i/f/o (tanh half-arg sigmoid), 1 for g-gate.
    //         h-consumers get extra 0.5 (published H = 2h):
    //           wh (all stages), wi (stages >= 1), w_lin.
    // wi columns absolute order (p-quad arrives absolute); wh columns j-rel.
    ull wiA0=0,wiA1=0,wiA2=0,wiA3=0, wiB0=0,wiB1=0,wiB2=0,wiB3=0;
    ull whA0=0,whA1=0,whA2=0,whA3=0, whB0=0,whB1=0,whB2=0,whB3=0;
    ull bp0=0, bp1=0, bp2=0, bp3=0;

    if (stage <= 4) {
        #define LQ(q, WIA, WIB, WHA, WHB, BP) do {                                 \
            const int   r  = (q) * 4 + j;                                          \
            const float sc = ((q) == 2) ? 1.0f : 0.5f;                             \
            float w0, w1, w2, w3;                                                  \
            if (stage == 0) {                                                      \
                w0 = sc * w_ih0[r * 2 + 0];  w1 = sc * w_ih0[r * 2 + 1];           \
                w2 = 0.0f;                   w3 = 0.0f;                            \
            } else {                                                               \
                const float* wp = w_ih + (((stage - 1) * 16) + r) * 4;             \
                const float s2 = sc * 0.5f;                                        \
                w0 = s2 * wp[0]; w1 = s2 * wp[1]; w2 = s2 * wp[2]; w3 = s2 * wp[3];\
            }                                                                      \
            WIA = pk2(w0, w1);  WIB = pk2(w2, w3);                                 \
            const float* hp = w_hh + ((stage * 16) + r) * 4;                       \
            const float sh = sc * 0.5f;                                            \
            WHA = pk2(sh * hp[j ^ 0], sh * hp[j ^ 1]);                             \
            WHB = pk2(sh * hp[j ^ 2], sh * hp[j ^ 3]);                             \
            BP  = pk2(sc * (b_ih[stage * 16 + r] + b_hh[stage * 16 + r]), 0.0f);   \
        } while (0)
        LQ(0, wiA0, wiB0, whA0, whB0, bp0);
        LQ(1, wiA1, wiB1, whA1, whB1, bp1);
        LQ(2, wiA2, wiB2, whA2, whB2, bp2);
        LQ(3, wiA3, wiB3, whA3, whB3, bp3);
        #undef LQ
    } else if (stage == 5) {
        wiA0 = pk2(0.5f * w_lin[0], 0.5f * w_lin[1]);   // consumes 2h of layer 4
        wiB0 = pk2(0.5f * w_lin[2], 0.5f * w_lin[3]);
        bp0  = pk2(b_lin[0], 0.0f);
    }

    // ---- SMEM staging ----
    __shared__ __align__(16) float2 xs2[XS_N];   // [0..609]=x, rest 0
    __shared__ __align__(8)  float  wfc_s[5][WFC_N];  // [10..619]=w_fc row, rest 0
    {
        const float2* xb2 = reinterpret_cast<const float2*>(x + (size_t)b * SEQ * 2);
        for (int i = lane; i < XS_N; i += 32)
            xs2[i] = (i < SEQ) ? xb2[i] : make_float2(0.0f, 0.0f);
        #pragma unroll
        for (int r = 0; r < 5; ++r)
            for (int i = lane; i < WFC_N; i += 32)
                wfc_s[r][i] = (i >= 10 && i < SEQ + 10) ? w_fc[r * SEQ + (i - 10)] : 0.0f;
    }
    __syncwarp();

    const float* wA = wfc_s[(stage == 5) ? j : 0];
    const float* w4 = wfc_s[4];
    float accA = (stage == 5) ? b_fc[j] : 0.0f;
    float accB = (lane == 20) ? b_fc[4] : 0.0f;

    // ---- state: published H = 2h for the round's two timesteps ----
    float hpubA = 0.0f, hpubB = 0.0f, cj = 0.0f;

    // one LSTM cell; publishes HOUT = 2h, keeps cj unscaled.
    #define CELL(PA, PB, HA, HB, CN, HOUT, G0OUT) do {                             \
        const float g0 = hadd2(fma2(whB0, HB, fma2(whA0, HA,                       \
                               fma2(wiB0, PB, fma2(wiA0, PA, bp0)))));             \
        const float g1 = hadd2(fma2(whB1, HB, fma2(whA1, HA,                       \
                               fma2(wiB1, PB, fma2(wiA1, PA, bp1)))));             \
        const float g2 = hadd2(fma2(whB2, HB, fma2(whA2, HA,                       \
                               fma2(wiB2, PB, fma2(wiA2, PA, bp2)))));             \
        const float g3 = hadd2(fma2(whB3, HB, fma2(whA3, HA,                       \
                               fma2(wiB3, PB, fma2(wiA3, PA, bp3)))));             \
        const float gt = tanh_fast(g2);                                            \
        const float T0 = tanh_fast(g0);                                            \
        const float T1 = tanh_fast(g1);                                            \
        const float T3 = tanh_fast(g3);                                            \
        const float u  = fmaf(T1, cj, cj);                                         \
        const float v  = fmaf(T0, gt, gt);                                         \
        CN = 0.5f * (u + v);                                                       \
        const float tc = tanh_fast(CN);                                            \
        HOUT = fmaf(T3, tc, tc);                                                   \
        G0OUT = g0;                                                                \
    } while (0)

    // one round = two timesteps t0 = 2r - 2*stage, t1 = t0+1
    #define ROUND(r, GUARD) do {                                                   \
        const int i0 = 2 * (r);                                                    \
        const float4 xq  = *reinterpret_cast<const float4*>(&xs2[i0]);             \
        const float2 wfa = *reinterpret_cast<const float2*>(&wA[i0]);              \
        const float2 wf4 = *reinterpret_cast<const float2*>(&w4[i0]);              \
        /* round-start shuffles (all parallel off hpubA/hpubB) */                  \
        const float ob1 = __shfl_xor_sync(0xffffffffu, hpubB, 1);                  \
        const float ob2 = __shfl_xor_sync(0xffffffffu, hpubB, 2);                  \
        const float ob3 = __shfl_xor_sync(0xffffffffu, hpubB, 3);                  \
        const float pA0 = __shfl_sync(0xffffffffu, hpubA, pbase);                  \
        const float pA1 = __shfl_sync(0xffffffffu, hpubA, pbase + 1);              \
        const float pA2 = __shfl_sync(0xffffffffu, hpubA, pbase + 2);              \
        const float pA3 = __shfl_sync(0xffffffffu, hpubA, pbase + 3);              \
        const float pB0 = __shfl_sync(0xffffffffu, hpubB, pbase);                  \
        const float pB1 = __shfl_sync(0xffffffffu, hpubB, pbase + 1);              \
        const float pB2 = __shfl_sync(0xffffffffu, hpubB, pbase + 2);              \
        const float pB3 = __shfl_sync(0xffffffffu, hpubB, pbase + 3);              \
        /* cell t0: stage 0 takes x directly (select off the h-chain) */           \
        const ull PAc0 = isS0 ? pk2(xq.x, xq.y) : pk2(pA0, pA1);                   \
        const ull PBc0 = isS0 ? 0ull            : pk2(pA2, pA3);                   \
        float cn0, hA2, g0c0;                                                      \
        CELL(PAc0, PBc0, pk2(hpubB, ob1), pk2(ob2, ob3), cn0, hA2, g0c0);          \
        float hAn;                                                                 \
        if (GUARD) {                                                               \
            const bool tv = (r) >= stage;                                          \
            cj  = tv ? cn0 : cj;                                                   \
            hAn = tv ? hA2 : 0.0f;                                                 \
        } else { cj = cn0; hAn = hA2; }                                            \
        /* intra-round gather of H(t0) */                                          \
        const float a1 = __shfl_xor_sync(0xffffffffu, hAn, 1);                     \
        const float a2 = __shfl_xor_sync(0xffffffffu, hAn, 2);                     \
        const float a3 = __shfl_xor_sync(0xffffffffu, hAn, 3);                     \
        /* cell t1 */                                                              \
        const ull PAc1 = isS0 ? pk2(xq.z, xq.w) : pk2(pB0, pB1);                   \
        const ull PBc1 = isS0 ? 0ull            : pk2(pB2, pB3);                   \
        float cn1, hB2, g0c1;                                                      \
        CELL(PAc1, PBc1, pk2(hAn, a1), pk2(a2, a3), cn1, hB2, g0c1);               \
        float hBn;                                                                 \
        if (GUARD) {                                                               \
            const bool tv = (r) >= stage;                                          \
            cj  = tv ? cn1 : cj;                                                   \
            hBn = tv ? hB2 : 0.0f;                                                 \
        } else { cj = cn1; hBn = hB2; }                                            \
        /* FC accumulate (stage5 g0 = Linear preactivation; zero-headed wfc) */    \
        accA = fmaf(wfa.x, g0c0, accA);                                            \
        accA = fmaf(wfa.y, g0c1, accA);                                            \
        accB = fmaf(wf4.x, g0c0, accB);                                            \
        accB = fmaf(wf4.y, g0c1, accB);                                            \
        hpubA = hAn;                                                               \
        hpubB = hBn;                                                               \
    } while (0)

    // prologue: guarded (t0 < 0 for stage > r)
    #pragma unroll 1
    for (int r = 0; r < 5; ++r) ROUND(r, true);
    // steady + tail: select-free (zero-padded x and wfc rows absorb overrun)
    #pragma unroll 2
    for (int r = 5; r < ROUNDS; ++r) ROUND(r, false);

    #undef ROUND
    #undef CELL

    if (stage == 5) out[b * 5 + j] = accA;
    if (lane == 20) out[b * 5 + 4] = accB;
}

extern "C" void kernel_launch(void* const* d_in, const int* in_sizes, int n_in,
                              void* d_out, int out_size) {
    const float* x     = (const float*)d_in[0];
    const float* w_ih0 = (const float*)d_in[1];
    const float* w_ih  = (const float*)d_in[2];
    const float* w_hh  = (const float*)d_in[3];
    const float* b_ih  = (const float*)d_in[4];
    const float* b_hh  = (const float*)d_in[5];
    const float* w_lin = (const float*)d_in[6];
    const float* b_lin = (const float*)d_in[7];
    const float* w_fc  = (const float*)d_in[8];
    const float* b_fc  = (const float*)d_in[9];
    float* out = (float*)d_out;

    lstm_warp_kernel<<<BATCH, 32>>>(
        x, w_ih0, w_ih, w_hh, b_ih, b_hh, w_lin, b_lin, w_fc, b_fc, out);
}